// round 16
// baseline (speedup 1.0000x reference)
#include <cuda_runtime.h>
#include <cstdint>

// HierarchicalRouter: two-level MoE router.
//   x [16384,2048] f32; group_gate_w [8,2048]; expert_gate_w [64,2048]
// out = concat(valid_mask[16384,64] as f32, normalized_weights[16384,64])
//
// R8 (2nd retry; broker timeouts, never ran): R5's compute tile (4 tokens x
// 9 experts per thread, k-pair FFMA2) with the LDG->register->STS staging
// replaced by cp.async (LDGSTS) into a 3-stage smem ring. No staging
// registers, no LDG->STS scoreboard chain; wait_group(1) gives each tile
// ~2 compute phases of memory-latency slack.
// (tcgen05 unusable: harness PTX targets compute_103, no 'a' features.)

#define N_TOKENS 16384
#define DIM      2048
#define BM       128
#define BK       16
#define BKK      8
#define NITER    (DIM / BK)     // 128
#define NSTAGE   3
#define THREADS  256
#define LSTRIDE  73
#define WGP      10             // padded u64 per expert group row

typedef unsigned long long u64;

__device__ __forceinline__ void ffma2(u64& acc, u64 a, u64 b) {
    asm("fma.rn.f32x2 %0, %1, %2, %0;" : "+l"(acc) : "l"(a), "l"(b));
}
__device__ __forceinline__ uint32_t smem_u32(const void* p) {
    uint32_t a;
    asm("{ .reg .u64 t; cvta.to.shared.u64 t, %1; cvt.u32.u64 %0, t; }"
        : "=r"(a) : "l"(p));
    return a;
}
__device__ __forceinline__ void cpa8(uint32_t dst, const float* src) {
    asm volatile("cp.async.ca.shared.global [%0], [%1], 8;"
                 :: "r"(dst), "l"(src) : "memory");
}
#define CPA_COMMIT() asm volatile("cp.async.commit_group;" ::: "memory")
#define CPA_WAIT1()  asm volatile("cp.async.wait_group 1;" ::: "memory")
#define CPA_WAIT0()  asm volatile("cp.async.wait_group 0;" ::: "memory")

struct SmemTiles {
    u64 xs[NSTAGE][BKK][BM];        // x k-pairs [stage][kk][token]  24 KB
    u64 ws[NSTAGE][BKK][8 * WGP];   // w k-pairs [stage][kk][g*10+j] 15 KB
};

__global__ __launch_bounds__(THREADS, 1)
void router_kernel(const float* __restrict__ x,
                   const float* __restrict__ ggw,
                   const float* __restrict__ egw,
                   float* __restrict__ out)
{
    __shared__ __align__(16) union {
        SmemTiles t;
        float logits[BM * LSTRIDE];  // reused after mainloop (37.4 KB)
    } sm;

    const int tid  = threadIdx.x;
    const int tg   = tid & 31;         // lane
    const int wid  = tid >> 5;         // expert group 0..7
    const int e0   = wid * 9;
    const int tok0 = blockIdx.x * BM;

    // ---- x copier mapping: tok = tid>>1, kk-half h = tid&1 ----
    const int ctok = tid >> 1;
    const int ch   = (tid & 1) * 4;    // kk base 0 or 4
    const float* xsrc = x + (size_t)(tok0 + ctok) * DIM + ch * 2;

    // ---- w copier: e = tid>>2 (0..63), q = tid&3 -> kk pairs 2q,2q+1 ----
    const int we0 = tid >> 2;
    const int wq0 = tid & 3;
    const float* wsrc0 = ((we0 < 8) ? (ggw + (size_t)we0 * DIM)
                                    : (egw + (size_t)(we0 - 8) * DIM)) + wq0 * 4;
    const int wd0 = (we0 / 9) * WGP + (we0 % 9);
    const int we1 = (tid + 256) >> 2;  // 64..71 (tid<32 only)
    const int wq1 = (tid + 256) & 3;
    const float* wsrc1 = egw + (size_t)(we1 - 8) * DIM + wq1 * 4;
    const int wd1 = (we1 / 9) * WGP + (we1 % 9);

    // smem byte addresses
    const uint32_t xs0 = smem_u32(&sm.t.xs[0][0][0]);
    const uint32_t ws0 = smem_u32(&sm.t.ws[0][0][0]);
    // per-stage strides in bytes
    const uint32_t XST = BKK * BM * 8;        // 8192
    const uint32_t WST = BKK * 8 * WGP * 8;   // 5120

    u64 acc[4][9];
#pragma unroll
    for (int m = 0; m < 4; m++)
#pragma unroll
        for (int j = 0; j < 9; j++) acc[m][j] = 0ull;

    auto issue_tile = [&](int t, int s) {
        const float* xp = xsrc + t * BK;
        const uint32_t xb = xs0 + s * XST + ctok * 8;
#pragma unroll
        for (int j = 0; j < 4; j++)
            cpa8(xb + (ch + j) * (BM * 8), xp + j * 2);
        const float* wp = wsrc0 + t * BK;
        const uint32_t wb = ws0 + s * WST;
        cpa8(wb + (2 * wq0 + 0) * (8 * WGP * 8) + wd0 * 8, wp + 0);
        cpa8(wb + (2 * wq0 + 1) * (8 * WGP * 8) + wd0 * 8, wp + 2);
        if (tid < 32) {
            const float* wq = wsrc1 + t * BK;
            cpa8(wb + (2 * wq1 + 0) * (8 * WGP * 8) + wd1 * 8, wq + 0);
            cpa8(wb + (2 * wq1 + 1) * (8 * WGP * 8) + wd1 * 8, wq + 2);
        }
        CPA_COMMIT();
    };

    auto compute = [&](int s) {
#pragma unroll
        for (int kk = 0; kk < BKK; kk++) {
            const u64 x0 = sm.t.xs[s][kk][tg];
            const u64 x1 = sm.t.xs[s][kk][tg + 32];
            const u64 x2 = sm.t.xs[s][kk][tg + 64];
            const u64 x3 = sm.t.xs[s][kk][tg + 96];
            const u64* wr = &sm.t.ws[s][kk][wid * WGP];
            const ulonglong2 w01 = *reinterpret_cast<const ulonglong2*>(wr + 0);
            const ulonglong2 w23 = *reinterpret_cast<const ulonglong2*>(wr + 2);
            const ulonglong2 w45 = *reinterpret_cast<const ulonglong2*>(wr + 4);
            const ulonglong2 w67 = *reinterpret_cast<const ulonglong2*>(wr + 6);
            const u64 w8 = wr[8];

            ffma2(acc[0][0], x0, w01.x); ffma2(acc[1][0], x1, w01.x);
            ffma2(acc[2][0], x2, w01.x); ffma2(acc[3][0], x3, w01.x);
            ffma2(acc[0][1], x0, w01.y); ffma2(acc[1][1], x1, w01.y);
            ffma2(acc[2][1], x2, w01.y); ffma2(acc[3][1], x3, w01.y);
            ffma2(acc[0][2], x0, w23.x); ffma2(acc[1][2], x1, w23.x);
            ffma2(acc[2][2], x2, w23.x); ffma2(acc[3][2], x3, w23.x);
            ffma2(acc[0][3], x0, w23.y); ffma2(acc[1][3], x1, w23.y);
            ffma2(acc[2][3], x2, w23.y); ffma2(acc[3][3], x3, w23.y);
            ffma2(acc[0][4], x0, w45.x); ffma2(acc[1][4], x1, w45.x);
            ffma2(acc[2][4], x2, w45.x); ffma2(acc[3][4], x3, w45.x);
            ffma2(acc[0][5], x0, w45.y); ffma2(acc[1][5], x1, w45.y);
            ffma2(acc[2][5], x2, w45.y); ffma2(acc[3][5], x3, w45.y);
            ffma2(acc[0][6], x0, w67.x); ffma2(acc[1][6], x1, w67.x);
            ffma2(acc[2][6], x2, w67.x); ffma2(acc[3][6], x3, w67.x);
            ffma2(acc[0][7], x0, w67.y); ffma2(acc[1][7], x1, w67.y);
            ffma2(acc[2][7], x2, w67.y); ffma2(acc[3][7], x3, w67.y);
            ffma2(acc[0][8], x0, w8);    ffma2(acc[1][8], x1, w8);
            ffma2(acc[2][8], x2, w8);    ffma2(acc[3][8], x3, w8);
        }
    };

    // ---- 3-stage cp.async ring ----
    issue_tile(0, 0);
    issue_tile(1, 1);

#pragma unroll 1
    for (int t = 0; t < NITER; ++t) {
        const int s = t % NSTAGE;
        if (t + 2 < NITER) CPA_WAIT1(); else CPA_WAIT0();
        __syncthreads();
        compute(s);
        if (t + 2 < NITER) {
            // stage (t+2)%NSTAGE held tile t-1; all threads are past it
            issue_tile(t + 2, (t + 2) % NSTAGE);
        }
    }
    __syncthreads();

    // ---- stage logits: sum even/odd k halves ----
#pragma unroll
    for (int m = 0; m < 4; m++) {
        const int tok = tg + 32 * m;
#pragma unroll
        for (int j = 0; j < 9; j++) {
            float2 p = *reinterpret_cast<float2*>(&acc[m][j]);
            sm.logits[tok * LSTRIDE + e0 + j] = p.x + p.y;
        }
    }
    __syncthreads();

    // ---- epilogue: one thread per token ----
    if (tid < BM) {
        float* L = &sm.logits[tid * LSTRIDE];  // [0..7] group, [8..71] expert

        float gl[8];
#pragma unroll
        for (int g = 0; g < 8; g++) gl[g] = L[g];
        float gmax = gl[0];
#pragma unroll
        for (int g = 1; g < 8; g++) gmax = fmaxf(gmax, gl[g]);
        float ge[8], gsum = 0.0f;
#pragma unroll
        for (int g = 0; g < 8; g++) { ge[g] = expf(gl[g] - gmax); gsum += ge[g]; }
        float gp[8];
#pragma unroll
        for (int g = 0; g < 8; g++) gp[g] = ge[g] / gsum;

        u64 vmask = 0ull;
        float swsum = 0.0f;
#pragma unroll
        for (int g = 0; g < 8; g++) {
            const bool gm = (gp[g] >= 0.125f);
            float el[8];
#pragma unroll
            for (int e = 0; e < 8; e++) el[e] = L[8 + g * 8 + e];
            float emax = el[0];
#pragma unroll
            for (int e = 1; e < 8; e++) emax = fmaxf(emax, el[e]);
            float ee[8], esum = 0.0f;
#pragma unroll
            for (int e = 0; e < 8; e++) { ee[e] = expf(el[e] - emax); esum += ee[e]; }
#pragma unroll
            for (int e = 0; e < 8; e++) {
                const float ep = ee[e] / esum;
                const bool val = gm && (ep >= 0.125f);
                const float sw = val ? gp[g] * ep : 0.0f;
                swsum += sw;
                L[8 + g * 8 + e] = sw;
                if (val) vmask |= (1ull << (g * 8 + e));
            }
        }
        swsum = fmaxf(swsum, 1e-9f);
        const float inv = 1.0f / swsum;

        const int gt = tok0 + tid;
        float* om = out + (size_t)gt * 64;
        float* ow = out + (size_t)N_TOKENS * 64 + (size_t)gt * 64;
#pragma unroll
        for (int i = 0; i < 64; i += 4) {
            float4 m4, w4;
            m4.x = ((vmask >> (i + 0)) & 1ull) ? 1.0f : 0.0f;
            m4.y = ((vmask >> (i + 1)) & 1ull) ? 1.0f : 0.0f;
            m4.z = ((vmask >> (i + 2)) & 1ull) ? 1.0f : 0.0f;
            m4.w = ((vmask >> (i + 3)) & 1ull) ? 1.0f : 0.0f;
            w4.x = L[8 + i + 0] * inv;
            w4.y = L[8 + i + 1] * inv;
            w4.z = L[8 + i + 2] * inv;
            w4.w = L[8 + i + 3] * inv;
            *reinterpret_cast<float4*>(om + i) = m4;
            *reinterpret_cast<float4*>(ow + i) = w4;
        }
    }
}

extern "C" void kernel_launch(void* const* d_in, const int* in_sizes, int n_in,
                              void* d_out, int out_size) {
    const float* x   = (const float*)d_in[0];
    const float* ggw = (const float*)d_in[1];
    const float* egw = (const float*)d_in[2];
    float* out = (float*)d_out;

    const int tokens = in_sizes[0] / DIM;   // 16384
    const int grid = tokens / BM;           // 128
    router_kernel<<<grid, THREADS>>>(x, ggw, egw, out);
}

// round 17
// speedup vs baseline: 1.1814x; 1.1814x over previous
#include <cuda_runtime.h>
#include <cstdint>

// HierarchicalRouter: two-level MoE router.
//   x [16384,2048] f32; group_gate_w [8,2048]; expert_gate_w [64,2048]
// out = concat(valid_mask[16384,64] as f32, normalized_weights[16384,64])
//
// R9 = R5's winning structure (4-deep pipeline: 2 reg + 2 smem stages, LDG
// issued 2 tiles ahead; 4 tokens x 9 experts per thread, k-pair FFMA2) with
// BK=32: 64 barrier phases instead of 128, amortizing the per-phase fixed
// overhead (barrier spread + LDS warm-up) over 2x the compute.
// smem 52.5KB -> dynamic. (R8's cp.async regressed: 8B LDGSTS too slow.)

#define N_TOKENS 16384
#define DIM      2048
#define BM       128
#define BK       32
#define BKK      16
#define NITER    (DIM / BK)     // 64
#define THREADS  256
#define LSTRIDE  73
#define XROW     130            // padded token row (u64)
#define WGP      10             // padded u64 per expert group (16B-aligned)

#define XS_STRIDE (BKK * XROW)          // u64 per x buffer: 2080
#define WS_BASE   (2 * XS_STRIDE)       // u64 offset of w region: 4160
#define WS_STRIDE (BKK * 8 * WGP)       // u64 per w buffer: 1280
#define SMEM_U64  (WS_BASE + 2 * WS_STRIDE)   // 6720 u64 = 53760 B
#define SMEM_BYTES (SMEM_U64 * 8)

typedef unsigned long long u64;

__device__ __forceinline__ void ffma2(u64& acc, u64 a, u64 b) {
    asm("fma.rn.f32x2 %0, %1, %2, %0;" : "+l"(acc) : "l"(a), "l"(b));
}

struct Stage {
    float4 xa[4];   // 4 rows x 16B chunk of x
    float4 wa[3];   // weight chunks (wa[2] only tid<64)
};

__global__ __launch_bounds__(THREADS, 1)
void router_kernel(const float* __restrict__ x,
                   const float* __restrict__ ggw,
                   const float* __restrict__ egw,
                   float* __restrict__ out)
{
    extern __shared__ __align__(16) u64 dsm[];

    const int tid  = threadIdx.x;
    const int tg   = tid & 31;         // lane
    const int wid  = tid >> 5;         // expert group 0..7
    const int e0   = wid * 9;
    const int tok0 = blockIdx.x * BM;

    // ---- x loader: chunk xc = tid&7 (16B of the 128B tile-row),
    //      base row xr = tid>>3 (0..31), rows xr+32i ----
    const int xc = tid & 7;
    const int xr = tid >> 3;
    const float* xbase = x + (size_t)(tok0 + xr) * DIM + xc * 4;

    // ---- w loader: idx -> e = idx>>3, q = idx&7 ----
    const int wq = tid & 7;
    const int we0 = tid >> 3;                 // 0..31
    const int we1 = we0 + 32;                 // 32..63
    const int we2 = we0 + 64;                 // 64..71 (tid<64)
    const float* wp0 = ((we0 < 8) ? (ggw + (size_t)we0 * DIM)
                                  : (egw + (size_t)(we0 - 8) * DIM)) + wq * 4;
    const float* wp1 = egw + (size_t)(we1 - 8) * DIM + wq * 4;
    const float* wp2 = (tid < 64) ? (egw + (size_t)(we2 - 8) * DIM + wq * 4)
                                  : nullptr;
    const int wd0 = (we0 / 9) * WGP + (we0 % 9);
    const int wd1 = (we1 / 9) * WGP + (we1 % 9);
    const int wd2 = (we2 / 9) * WGP + (we2 % 9);

    u64 acc[4][9];
#pragma unroll
    for (int m = 0; m < 4; m++)
#pragma unroll
        for (int j = 0; j < 9; j++) acc[m][j] = 0ull;

    auto ldg_tile = [&](int it, Stage& s) {
        const int k0 = it * BK;
#pragma unroll
        for (int i = 0; i < 4; i++)
            s.xa[i] = *reinterpret_cast<const float4*>(
                xbase + (size_t)(32 * i) * DIM + k0);
        s.wa[0] = *reinterpret_cast<const float4*>(wp0 + k0);
        s.wa[1] = *reinterpret_cast<const float4*>(wp1 + k0);
        if (tid < 64)
            s.wa[2] = *reinterpret_cast<const float4*>(wp2 + k0);
    };

    auto sts_tile = [&](int b, const Stage& s) {
        u64* xs = dsm + b * XS_STRIDE;
#pragma unroll
        for (int i = 0; i < 4; i++) {
            const int row = xr + 32 * i;
            *reinterpret_cast<float2*>(&xs[(xc * 2 + 0) * XROW + row]) =
                make_float2(s.xa[i].x, s.xa[i].y);
            *reinterpret_cast<float2*>(&xs[(xc * 2 + 1) * XROW + row]) =
                make_float2(s.xa[i].z, s.xa[i].w);
        }
        u64* ws = dsm + WS_BASE + b * WS_STRIDE;
        *reinterpret_cast<float2*>(&ws[(wq * 2 + 0) * (8 * WGP) + wd0]) =
            make_float2(s.wa[0].x, s.wa[0].y);
        *reinterpret_cast<float2*>(&ws[(wq * 2 + 1) * (8 * WGP) + wd0]) =
            make_float2(s.wa[0].z, s.wa[0].w);
        *reinterpret_cast<float2*>(&ws[(wq * 2 + 0) * (8 * WGP) + wd1]) =
            make_float2(s.wa[1].x, s.wa[1].y);
        *reinterpret_cast<float2*>(&ws[(wq * 2 + 1) * (8 * WGP) + wd1]) =
            make_float2(s.wa[1].z, s.wa[1].w);
        if (tid < 64) {
            *reinterpret_cast<float2*>(&ws[(wq * 2 + 0) * (8 * WGP) + wd2]) =
                make_float2(s.wa[2].x, s.wa[2].y);
            *reinterpret_cast<float2*>(&ws[(wq * 2 + 1) * (8 * WGP) + wd2]) =
                make_float2(s.wa[2].z, s.wa[2].w);
        }
    };

    auto compute = [&](int b) {
        const u64* xs = dsm + b * XS_STRIDE;
        const u64* ws = dsm + WS_BASE + b * WS_STRIDE;
#pragma unroll
        for (int kk = 0; kk < BKK; kk++) {
            const u64* xrow_s = &xs[kk * XROW];
            const u64 x0 = xrow_s[tg];
            const u64 x1 = xrow_s[tg + 32];
            const u64 x2 = xrow_s[tg + 64];
            const u64 x3 = xrow_s[tg + 96];
            const u64* wr = &ws[kk * (8 * WGP) + wid * WGP];
            const ulonglong2 w01 = *reinterpret_cast<const ulonglong2*>(wr + 0);
            const ulonglong2 w23 = *reinterpret_cast<const ulonglong2*>(wr + 2);
            const ulonglong2 w45 = *reinterpret_cast<const ulonglong2*>(wr + 4);
            const ulonglong2 w67 = *reinterpret_cast<const ulonglong2*>(wr + 6);
            const u64 w8 = wr[8];

            ffma2(acc[0][0], x0, w01.x); ffma2(acc[1][0], x1, w01.x);
            ffma2(acc[2][0], x2, w01.x); ffma2(acc[3][0], x3, w01.x);
            ffma2(acc[0][1], x0, w01.y); ffma2(acc[1][1], x1, w01.y);
            ffma2(acc[2][1], x2, w01.y); ffma2(acc[3][1], x3, w01.y);
            ffma2(acc[0][2], x0, w23.x); ffma2(acc[1][2], x1, w23.x);
            ffma2(acc[2][2], x2, w23.x); ffma2(acc[3][2], x3, w23.x);
            ffma2(acc[0][3], x0, w23.y); ffma2(acc[1][3], x1, w23.y);
            ffma2(acc[2][3], x2, w23.y); ffma2(acc[3][3], x3, w23.y);
            ffma2(acc[0][4], x0, w45.x); ffma2(acc[1][4], x1, w45.x);
            ffma2(acc[2][4], x2, w45.x); ffma2(acc[3][4], x3, w45.x);
            ffma2(acc[0][5], x0, w45.y); ffma2(acc[1][5], x1, w45.y);
            ffma2(acc[2][5], x2, w45.y); ffma2(acc[3][5], x3, w45.y);
            ffma2(acc[0][6], x0, w67.x); ffma2(acc[1][6], x1, w67.x);
            ffma2(acc[2][6], x2, w67.x); ffma2(acc[3][6], x3, w67.x);
            ffma2(acc[0][7], x0, w67.y); ffma2(acc[1][7], x1, w67.y);
            ffma2(acc[2][7], x2, w67.y); ffma2(acc[3][7], x3, w67.y);
            ffma2(acc[0][8], x0, w8);    ffma2(acc[1][8], x1, w8);
            ffma2(acc[2][8], x2, w8);    ffma2(acc[3][8], x3, w8);
        }
    };

    // ---- 4-deep pipeline: 2 reg stages + 2 smem stages ----
    Stage P, Q;
    ldg_tile(0, P);
    ldg_tile(1, Q);
    sts_tile(0, P);
    __syncthreads();

    int cur = 0;
#pragma unroll 1
    for (int it = 0; it < NITER; it += 2) {
        if (it + 2 < NITER) ldg_tile(it + 2, P);
        compute(cur);
        if (it + 1 < NITER) sts_tile(cur ^ 1, Q);
        __syncthreads();
        cur ^= 1;
        if (it + 3 < NITER) ldg_tile(it + 3, Q);
        compute(cur);
        if (it + 2 < NITER) sts_tile(cur ^ 1, P);
        __syncthreads();
        cur ^= 1;
    }

    // ---- stage logits into (reused) dynamic smem ----
    float* logits = reinterpret_cast<float*>(dsm);
#pragma unroll
    for (int m = 0; m < 4; m++) {
        const int tok = tg + 32 * m;
#pragma unroll
        for (int j = 0; j < 9; j++) {
            float2 p = *reinterpret_cast<float2*>(&acc[m][j]);
            logits[tok * LSTRIDE + e0 + j] = p.x + p.y;
        }
    }
    __syncthreads();

    // ---- epilogue: one thread per token ----
    if (tid < BM) {
        float* L = &logits[tid * LSTRIDE];  // [0..7] group, [8..71] expert

        float gl[8];
#pragma unroll
        for (int g = 0; g < 8; g++) gl[g] = L[g];
        float gmax = gl[0];
#pragma unroll
        for (int g = 1; g < 8; g++) gmax = fmaxf(gmax, gl[g]);
        float ge[8], gsum = 0.0f;
#pragma unroll
        for (int g = 0; g < 8; g++) { ge[g] = expf(gl[g] - gmax); gsum += ge[g]; }
        float gp[8];
#pragma unroll
        for (int g = 0; g < 8; g++) gp[g] = ge[g] / gsum;

        u64 vmask = 0ull;
        float swsum = 0.0f;
#pragma unroll
        for (int g = 0; g < 8; g++) {
            const bool gm = (gp[g] >= 0.125f);
            float el[8];
#pragma unroll
            for (int e = 0; e < 8; e++) el[e] = L[8 + g * 8 + e];
            float emax = el[0];
#pragma unroll
            for (int e = 1; e < 8; e++) emax = fmaxf(emax, el[e]);
            float ee[8], esum = 0.0f;
#pragma unroll
            for (int e = 0; e < 8; e++) { ee[e] = expf(el[e] - emax); esum += ee[e]; }
#pragma unroll
            for (int e = 0; e < 8; e++) {
                const float ep = ee[e] / esum;
                const bool val = gm && (ep >= 0.125f);
                const float sw = val ? gp[g] * ep : 0.0f;
                swsum += sw;
                L[8 + g * 8 + e] = sw;
                if (val) vmask |= (1ull << (g * 8 + e));
            }
        }
        swsum = fmaxf(swsum, 1e-9f);
        const float inv = 1.0f / swsum;

        const int gt = tok0 + tid;
        float* om = out + (size_t)gt * 64;
        float* ow = out + (size_t)N_TOKENS * 64 + (size_t)gt * 64;
#pragma unroll
        for (int i = 0; i < 64; i += 4) {
            float4 m4, w4;
            m4.x = ((vmask >> (i + 0)) & 1ull) ? 1.0f : 0.0f;
            m4.y = ((vmask >> (i + 1)) & 1ull) ? 1.0f : 0.0f;
            m4.z = ((vmask >> (i + 2)) & 1ull) ? 1.0f : 0.0f;
            m4.w = ((vmask >> (i + 3)) & 1ull) ? 1.0f : 0.0f;
            w4.x = L[8 + i + 0] * inv;
            w4.y = L[8 + i + 1] * inv;
            w4.z = L[8 + i + 2] * inv;
            w4.w = L[8 + i + 3] * inv;
            *reinterpret_cast<float4*>(om + i) = m4;
            *reinterpret_cast<float4*>(ow + i) = w4;
        }
    }
}

extern "C" void kernel_launch(void* const* d_in, const int* in_sizes, int n_in,
                              void* d_out, int out_size) {
    const float* x   = (const float*)d_in[0];
    const float* ggw = (const float*)d_in[1];
    const float* egw = (const float*)d_in[2];
    float* out = (float*)d_out;

    cudaFuncSetAttribute(router_kernel,
                         cudaFuncAttributeMaxDynamicSharedMemorySize, SMEM_BYTES);
    const int tokens = in_sizes[0] / DIM;   // 16384
    const int grid = tokens / BM;           // 128
    router_kernel<<<grid, THREADS, SMEM_BYTES>>>(x, ggw, egw, out);
}